// round 1
// baseline (speedup 1.0000x reference)
#include <cuda_runtime.h>
#include <cstdint>

#define SEQ    2048
#define BATCH  4
#define DM     1024
#define NH     16
#define DH     64

// ---------------------------------------------------------------------------
// Scratch (allocation-free rule: __device__ globals)
// ---------------------------------------------------------------------------
__device__ float g_qkv[(size_t)BATCH * SEQ * 3 * DM];   // [B,S,3D]
__device__ float g_attn[(size_t)BATCH * SEQ * DM];      // [B,S,D]

#define NEG_INF (__int_as_float(0xff800000))

__device__ __forceinline__ uint32_t f2tf(float x) {
    uint32_t u;
    asm volatile("cvt.rna.tf32.f32 %0, %1;" : "=r"(u) : "f"(x));
    return u;
}
__device__ __forceinline__ float tf32r(float x) { return __uint_as_float(f2tf(x)); }

__device__ __forceinline__ void mma_tf32(float c[4],
    uint32_t a0, uint32_t a1, uint32_t a2, uint32_t a3,
    uint32_t b0, uint32_t b1)
{
    asm volatile(
        "mma.sync.aligned.m16n8k8.row.col.f32.tf32.tf32.f32 "
        "{%0,%1,%2,%3}, {%4,%5,%6,%7}, {%8,%9}, {%0,%1,%2,%3};\n"
        : "+f"(c[0]), "+f"(c[1]), "+f"(c[2]), "+f"(c[3])
        : "r"(a0), "r"(a1), "r"(a2), "r"(a3), "r"(b0), "r"(b1));
}

// ---------------------------------------------------------------------------
// GEMM: C[M,N] = A[M,K] @ B[K,N] + bias[N]   (row-major, tf32 tensor cores)
// Block tile 128x128, BK=32, 256 threads (8 warps, 4x2), warp tile 32x64.
// ---------------------------------------------------------------------------
#define BM 128
#define BN 128
#define BK 32
#define AS_LD 36     // pad: bank-conflict-free A-fragment loads
#define BS_LD 136    // pad: bank-conflict-free B-fragment loads

__global__ __launch_bounds__(256)
void gemm_bias_tf32(const float* __restrict__ A, const float* __restrict__ B,
                    const float* __restrict__ bias, float* __restrict__ C,
                    int M, int N, int K)
{
    __shared__ __align__(16) float As[BM * AS_LD];
    __shared__ __align__(16) float Bs[BK * BS_LD];

    const int tid  = threadIdx.x;
    const int warp = tid >> 5;
    const int lane = tid & 31;
    const int g    = lane >> 2;     // groupID (0..7)
    const int tg   = lane & 3;      // threadID_in_group (0..3)
    const int wm   = (warp >> 1) * 32;   // warp row offset in block tile
    const int wn   = (warp & 1) * 64;    // warp col offset
    const int bm0  = blockIdx.y * BM;
    const int bn0  = blockIdx.x * BN;

    float acc[2][8][4];
    #pragma unroll
    for (int mt = 0; mt < 2; mt++)
        #pragma unroll
        for (int j = 0; j < 8; j++)
            #pragma unroll
            for (int e = 0; e < 4; e++)
                acc[mt][j][e] = 0.f;

    for (int kt = 0; kt < K; kt += BK) {
        // Load A tile 128x32 (1024 float4s, 4 per thread)
        #pragma unroll
        for (int i = 0; i < 4; i++) {
            int idx = tid + i * 256;
            int r = idx >> 3;
            int c = (idx & 7) << 2;
            float4 v = *(const float4*)(A + (size_t)(bm0 + r) * K + kt + c);
            float4 w = make_float4(tf32r(v.x), tf32r(v.y), tf32r(v.z), tf32r(v.w));
            *(float4*)(As + r * AS_LD + c) = w;
        }
        // Load B tile 32x128 (1024 float4s)
        #pragma unroll
        for (int i = 0; i < 4; i++) {
            int idx = tid + i * 256;
            int r = idx >> 5;
            int c = (idx & 31) << 2;
            float4 v = *(const float4*)(B + (size_t)(kt + r) * N + bn0 + c);
            float4 w = make_float4(tf32r(v.x), tf32r(v.y), tf32r(v.z), tf32r(v.w));
            *(float4*)(Bs + r * BS_LD + c) = w;
        }
        __syncthreads();

        #pragma unroll
        for (int kk = 0; kk < BK; kk += 8) {
            uint32_t af[2][4], bf[8][2];
            #pragma unroll
            for (int mt = 0; mt < 2; mt++) {
                const float* p = As + (wm + mt * 16 + g) * AS_LD + kk + tg;
                af[mt][0] = __float_as_uint(p[0]);
                af[mt][1] = __float_as_uint(p[8 * AS_LD]);
                af[mt][2] = __float_as_uint(p[4]);
                af[mt][3] = __float_as_uint(p[8 * AS_LD + 4]);
            }
            #pragma unroll
            for (int j = 0; j < 8; j++) {
                const float* p = Bs + (kk + tg) * BS_LD + wn + j * 8 + g;
                bf[j][0] = __float_as_uint(p[0]);
                bf[j][1] = __float_as_uint(p[4 * BS_LD]);
            }
            #pragma unroll
            for (int mt = 0; mt < 2; mt++)
                #pragma unroll
                for (int j = 0; j < 8; j++)
                    mma_tf32(acc[mt][j], af[mt][0], af[mt][1], af[mt][2], af[mt][3],
                             bf[j][0], bf[j][1]);
        }
        __syncthreads();
    }

    // Epilogue: += bias, store
    #pragma unroll
    for (int mt = 0; mt < 2; mt++) {
        int r0 = bm0 + wm + mt * 16 + g;
        #pragma unroll
        for (int j = 0; j < 8; j++) {
            int c0 = bn0 + wn + j * 8 + tg * 2;
            float2 bb = *(const float2*)(bias + c0);
            float2 o0 = make_float2(acc[mt][j][0] + bb.x, acc[mt][j][1] + bb.y);
            float2 o1 = make_float2(acc[mt][j][2] + bb.x, acc[mt][j][3] + bb.y);
            *(float2*)(C + (size_t)r0 * N + c0) = o0;
            *(float2*)(C + (size_t)(r0 + 8) * N + c0) = o1;
        }
    }
}

// ---------------------------------------------------------------------------
// Flash attention: block = (64-query tile) x (b*h). 128 threads (4 warps).
// Warp w owns query rows 16w..16w+15 of the tile for BOTH QK^T and PV.
// Q fragments in registers; sQ region reused as P staging for PV mma.
// Dynamic smem: sQ/sP[64][68] + sK[64][68] + sV[64][72] = 53248 B.
// ---------------------------------------------------------------------------
#define QP_LD 68
#define K_LD  68
#define V_LD  72
#define ATTN_SMEM ((64 * QP_LD + 64 * K_LD + 64 * V_LD) * 4)

__global__ __launch_bounds__(128)
void attn_kernel()
{
    extern __shared__ __align__(16) float sm[];
    float* sQ = sm;                        // also P after softmax
    float* sK = sm + 64 * QP_LD;
    float* sV = sm + 64 * QP_LD + 64 * K_LD;

    const int tid  = threadIdx.x;
    const int warp = tid >> 5;
    const int lane = tid & 31;
    const int g    = lane >> 2;
    const int tg   = lane & 3;
    const int qt   = blockIdx.x;           // query tile (0..31)
    const int bh   = blockIdx.y;           // 0..63
    const int b    = bh >> 4;
    const int h    = bh & 15;

    const float* base = g_qkv + (size_t)b * SEQ * (3 * DM) + h * DH;  // q row ptr base

    // Load Q tile (64 rows x 64 cols), tf32-rounded
    for (int i = tid; i < 64 * 16; i += 128) {
        int r = i >> 4;
        int c = (i & 15) << 2;
        float4 v = *(const float4*)(base + (size_t)(qt * 64 + r) * (3 * DM) + c);
        float4 w = make_float4(tf32r(v.x), tf32r(v.y), tf32r(v.z), tf32r(v.w));
        *(float4*)(sQ + r * QP_LD + c) = w;
    }
    __syncthreads();

    // Q fragments for this warp's 16 rows (8 k-steps over dh=64)
    uint32_t qf[8][4];
    {
        const int m = warp * 16 + g;
        #pragma unroll
        for (int kk = 0; kk < 8; kk++) {
            const float* p = sQ + m * QP_LD + kk * 8 + tg;
            qf[kk][0] = __float_as_uint(p[0]);
            qf[kk][1] = __float_as_uint(p[8 * QP_LD]);
            qf[kk][2] = __float_as_uint(p[4]);
            qf[kk][3] = __float_as_uint(p[8 * QP_LD + 4]);
        }
    }
    __syncthreads();

    float o[8][4];
    #pragma unroll
    for (int j = 0; j < 8; j++)
        #pragma unroll
        for (int e = 0; e < 4; e++) o[j][e] = 0.f;
    float m0 = NEG_INF, m1 = NEG_INF, l0 = 0.f, l1 = 0.f;

    for (int kt = 0; kt <= qt; kt++) {
        __syncthreads();   // previous iteration's K/V readers done
        // Load K and V tiles (64 keys x 64 dh each), tf32-rounded
        const float* kbase = base + DM + (size_t)kt * 64 * (3 * DM);
        const float* vbase = kbase + DM;
        for (int i = tid; i < 64 * 16; i += 128) {
            int r = i >> 4;
            int c = (i & 15) << 2;
            float4 kv = *(const float4*)(kbase + (size_t)r * (3 * DM) + c);
            *(float4*)(sK + r * K_LD + c) =
                make_float4(tf32r(kv.x), tf32r(kv.y), tf32r(kv.z), tf32r(kv.w));
            float4 vv = *(const float4*)(vbase + (size_t)r * (3 * DM) + c);
            *(float4*)(sV + r * V_LD + c) =
                make_float4(tf32r(vv.x), tf32r(vv.y), tf32r(vv.z), tf32r(vv.w));
        }
        __syncthreads();

        // S = Q @ K^T  (warp rows 16, all 64 key cols)
        float c_[8][4];
        #pragma unroll
        for (int j = 0; j < 8; j++)
            #pragma unroll
            for (int e = 0; e < 4; e++) c_[j][e] = 0.f;

        #pragma unroll
        for (int kk = 0; kk < 8; kk++) {
            #pragma unroll
            for (int j = 0; j < 8; j++) {
                const float* p = sK + (j * 8 + g) * K_LD + kk * 8 + tg;
                mma_tf32(c_[j], qf[kk][0], qf[kk][1], qf[kk][2], qf[kk][3],
                         __float_as_uint(p[0]), __float_as_uint(p[4]));
            }
        }

        // scale (1/sqrt(64)) + causal mask on diagonal tile
        if (kt == qt) {
            #pragma unroll
            for (int j = 0; j < 8; j++) {
                #pragma unroll
                for (int e = 0; e < 4; e++) {
                    int col = j * 8 + tg * 2 + (e & 1);
                    int row = warp * 16 + g + (e >> 1) * 8;
                    c_[j][e] = (col > row) ? NEG_INF : c_[j][e] * 0.125f;
                }
            }
        } else {
            #pragma unroll
            for (int j = 0; j < 8; j++)
                #pragma unroll
                for (int e = 0; e < 4; e++) c_[j][e] *= 0.125f;
        }

        // online softmax (rows g and g+8 of this warp's 16)
        float rx0 = NEG_INF, rx1 = NEG_INF;
        #pragma unroll
        for (int j = 0; j < 8; j++) {
            rx0 = fmaxf(rx0, fmaxf(c_[j][0], c_[j][1]));
            rx1 = fmaxf(rx1, fmaxf(c_[j][2], c_[j][3]));
        }
        rx0 = fmaxf(rx0, __shfl_xor_sync(0xffffffffu, rx0, 1));
        rx0 = fmaxf(rx0, __shfl_xor_sync(0xffffffffu, rx0, 2));
        rx1 = fmaxf(rx1, __shfl_xor_sync(0xffffffffu, rx1, 1));
        rx1 = fmaxf(rx1, __shfl_xor_sync(0xffffffffu, rx1, 2));

        float mn0 = fmaxf(m0, rx0), mn1 = fmaxf(m1, rx1);
        float al0 = __expf(m0 - mn0), al1 = __expf(m1 - mn1);
        float s0 = 0.f, s1 = 0.f;
        #pragma unroll
        for (int j = 0; j < 8; j++) {
            c_[j][0] = __expf(c_[j][0] - mn0);
            c_[j][1] = __expf(c_[j][1] - mn0);
            c_[j][2] = __expf(c_[j][2] - mn1);
            c_[j][3] = __expf(c_[j][3] - mn1);
            s0 += c_[j][0] + c_[j][1];
            s1 += c_[j][2] + c_[j][3];
        }
        s0 += __shfl_xor_sync(0xffffffffu, s0, 1);
        s0 += __shfl_xor_sync(0xffffffffu, s0, 2);
        s1 += __shfl_xor_sync(0xffffffffu, s1, 1);
        s1 += __shfl_xor_sync(0xffffffffu, s1, 2);
        l0 = l0 * al0 + s0;
        l1 = l1 * al1 + s1;
        m0 = mn0; m1 = mn1;
        #pragma unroll
        for (int j = 0; j < 8; j++) {
            o[j][0] *= al0; o[j][1] *= al0;
            o[j][2] *= al1; o[j][3] *= al1;
        }

        // stage P (tf32) into per-warp rows of sQ, then PV mma
        {
            const int rl = warp * 16 + g;
            #pragma unroll
            for (int j = 0; j < 8; j++) {
                float* p0 = sQ + rl * QP_LD + j * 8 + tg * 2;
                p0[0] = tf32r(c_[j][0]);
                p0[1] = tf32r(c_[j][1]);
                float* p1 = sQ + (rl + 8) * QP_LD + j * 8 + tg * 2;
                p1[0] = tf32r(c_[j][2]);
                p1[1] = tf32r(c_[j][3]);
            }
        }
        __syncwarp();

        #pragma unroll
        for (int kk = 0; kk < 8; kk++) {
            const float* pa = sQ + (warp * 16 + g) * QP_LD + kk * 8 + tg;
            uint32_t a0 = __float_as_uint(pa[0]);
            uint32_t a1 = __float_as_uint(pa[8 * QP_LD]);
            uint32_t a2 = __float_as_uint(pa[4]);
            uint32_t a3 = __float_as_uint(pa[8 * QP_LD + 4]);
            #pragma unroll
            for (int j = 0; j < 8; j++) {
                const float* pb = sV + (kk * 8 + tg) * V_LD + j * 8 + g;
                mma_tf32(o[j], a0, a1, a2, a3,
                         __float_as_uint(pb[0]), __float_as_uint(pb[4 * V_LD]));
            }
        }
        __syncwarp();
    }

    // normalize and store: g_attn[b, s, h*64 + d]
    const float inv0 = 1.f / l0, inv1 = 1.f / l1;
    const int srow = qt * 64 + warp * 16 + g;
    float* out0 = g_attn + ((size_t)b * SEQ + srow) * DM + h * DH;
    float* out1 = g_attn + ((size_t)b * SEQ + srow + 8) * DM + h * DH;
    #pragma unroll
    for (int j = 0; j < 8; j++) {
        int cl = j * 8 + tg * 2;
        *(float2*)(out0 + cl) = make_float2(o[j][0] * inv0, o[j][1] * inv0);
        *(float2*)(out1 + cl) = make_float2(o[j][2] * inv1, o[j][3] * inv1);
    }
}

// ---------------------------------------------------------------------------
// Launch
// ---------------------------------------------------------------------------
extern "C" void kernel_launch(void* const* d_in, const int* in_sizes, int n_in,
                              void* d_out, int out_size)
{
    (void)in_sizes; (void)n_in; (void)out_size;
    const float* x     = (const float*)d_in[0];
    const float* w_in  = (const float*)d_in[1];
    const float* b_in  = (const float*)d_in[2];
    const float* w_out = (const float*)d_in[3];
    const float* b_out = (const float*)d_in[4];
    float* out = (float*)d_out;

    float* qkv  = nullptr;
    float* attn = nullptr;
    cudaGetSymbolAddress((void**)&qkv, g_qkv);
    cudaGetSymbolAddress((void**)&attn, g_attn);

    const int M = BATCH * SEQ;  // 8192

    // 1) QKV projection: [8192,1024] @ [1024,3072] + b_in
    gemm_bias_tf32<<<dim3((3 * DM) / BN, M / BM), 256>>>(x, w_in, b_in, qkv, M, 3 * DM, DM);

    // 2) causal flash attention
    cudaFuncSetAttribute(attn_kernel, cudaFuncAttributeMaxDynamicSharedMemorySize, ATTN_SMEM);
    attn_kernel<<<dim3(SEQ / 64, BATCH * NH), 128, ATTN_SMEM>>>();

    // 3) output projection: [8192,1024] @ [1024,1024] + b_out
    gemm_bias_tf32<<<dim3(DM / BN, M / BM), 256>>>(attn, w_out, b_out, out, M, DM, DM);
}

// round 2
// speedup vs baseline: 1.1337x; 1.1337x over previous
#include <cuda_runtime.h>
#include <cstdint>

#define SEQ    2048
#define BATCH  4
#define DM     1024
#define NH     16
#define DH     64

// ---------------------------------------------------------------------------
// Scratch (allocation-free rule: __device__ globals)
// ---------------------------------------------------------------------------
__device__ float g_qkv[(size_t)BATCH * SEQ * 3 * DM];   // [B,S,3D] (tf32-rounded)
__device__ float g_attn[(size_t)BATCH * SEQ * DM];      // [B,S,D]  (tf32-rounded)
__device__ float g_x[(size_t)BATCH * SEQ * DM];         // tf32(x)
__device__ float g_win[(size_t)DM * 3 * DM];            // tf32(w_in)
__device__ float g_wout[(size_t)DM * DM];               // tf32(w_out)

#define NEG_INF (__int_as_float(0xff800000))

__device__ __forceinline__ uint32_t f2tf(float x) {
    uint32_t u;
    asm volatile("cvt.rna.tf32.f32 %0, %1;" : "=r"(u) : "f"(x));
    return u;
}
__device__ __forceinline__ float tf32r(float x) { return __uint_as_float(f2tf(x)); }

__device__ __forceinline__ float ex2(float x) {
    float y;
    asm("ex2.approx.f32 %0, %1;" : "=f"(y) : "f"(x));
    return y;
}

__device__ __forceinline__ void mma_tf32(float c[4],
    uint32_t a0, uint32_t a1, uint32_t a2, uint32_t a3,
    uint32_t b0, uint32_t b1)
{
    asm volatile(
        "mma.sync.aligned.m16n8k8.row.col.f32.tf32.tf32.f32 "
        "{%0,%1,%2,%3}, {%4,%5,%6,%7}, {%8,%9}, {%0,%1,%2,%3};\n"
        : "+f"(c[0]), "+f"(c[1]), "+f"(c[2]), "+f"(c[3])
        : "r"(a0), "r"(a1), "r"(a2), "r"(a3), "r"(b0), "r"(b1));
}

__device__ __forceinline__ void cp16(float* s, const float* g) {
    uint32_t sa = (uint32_t)__cvta_generic_to_shared(s);
    asm volatile("cp.async.cg.shared.global [%0], [%1], 16;\n" :: "r"(sa), "l"(g));
}
__device__ __forceinline__ void cp_commit() {
    asm volatile("cp.async.commit_group;\n");
}
template <int N>
__device__ __forceinline__ void cp_wait() {
    asm volatile("cp.async.wait_group %0;\n" :: "n"(N));
}

// ---------------------------------------------------------------------------
// Elementwise tf32 rounding (pre-pass)
// ---------------------------------------------------------------------------
__global__ void round_tf32_kernel(const float* __restrict__ in,
                                  float* __restrict__ out, int n4)
{
    int i = blockIdx.x * blockDim.x + threadIdx.x;
    if (i < n4) {
        float4 v = ((const float4*)in)[i];
        ((float4*)out)[i] = make_float4(tf32r(v.x), tf32r(v.y), tf32r(v.z), tf32r(v.w));
    }
}

// ---------------------------------------------------------------------------
// GEMM: C[M,N] = A[M,K] @ B[K,N] + bias[N]
// Inputs pre-rounded tf32. 3-stage cp.async pipeline, 128x128x32 tile,
// 256 threads (8 warps, warp tile 32x64).
// ---------------------------------------------------------------------------
#define BM 128
#define BN 128
#define BK 32
#define AS_LD 36
#define BS_LD 136
#define A_STG (BM * AS_LD)   // 4608 floats
#define B_STG (BK * BS_LD)   // 4352 floats
#define STAGES 3
#define STG_FLOATS (A_STG + B_STG)
#define GEMM_SMEM (STAGES * STG_FLOATS * 4)   // 107520 bytes

__device__ __forceinline__ void gemm_load_stage(
    float* stg, const float* __restrict__ A, const float* __restrict__ B,
    int bm0, int bn0, int kt, int N, int K, int tid)
{
    float* As = stg;
    float* Bs = stg + A_STG;
    #pragma unroll
    for (int i = 0; i < 4; i++) {
        int idx = tid + i * 256;
        int r = idx >> 3;
        int c = (idx & 7) << 2;
        cp16(As + r * AS_LD + c, A + (size_t)(bm0 + r) * K + kt + c);
    }
    #pragma unroll
    for (int i = 0; i < 4; i++) {
        int idx = tid + i * 256;
        int r = idx >> 5;
        int c = (idx & 31) << 2;
        cp16(Bs + r * BS_LD + c, B + (size_t)(kt + r) * N + bn0 + c);
    }
}

__global__ __launch_bounds__(256, 2)
void gemm_bias_tf32(const float* __restrict__ A, const float* __restrict__ B,
                    const float* __restrict__ bias, float* __restrict__ C,
                    int M, int N, int K, int round_out)
{
    extern __shared__ __align__(16) float sm[];

    const int tid  = threadIdx.x;
    const int warp = tid >> 5;
    const int lane = tid & 31;
    const int g    = lane >> 2;
    const int tg   = lane & 3;
    const int wm   = (warp >> 1) * 32;
    const int wn   = (warp & 1) * 64;
    const int bm0  = blockIdx.y * BM;
    const int bn0  = blockIdx.x * BN;

    float acc[2][8][4];
    #pragma unroll
    for (int mt = 0; mt < 2; mt++)
        #pragma unroll
        for (int j = 0; j < 8; j++)
            #pragma unroll
            for (int e = 0; e < 4; e++)
                acc[mt][j][e] = 0.f;

    const int T = K / BK;

    // prologue: stages 0..STAGES-2
    #pragma unroll
    for (int s = 0; s < STAGES - 1; s++) {
        gemm_load_stage(sm + s * STG_FLOATS, A, B, bm0, bn0, s * BK, N, K, tid);
        cp_commit();
    }

    for (int t = 0; t < T; t++) {
        cp_wait<STAGES - 2>();
        __syncthreads();

        int tn = t + STAGES - 1;
        if (tn < T)
            gemm_load_stage(sm + (tn % STAGES) * STG_FLOATS, A, B, bm0, bn0, tn * BK, N, K, tid);
        cp_commit();

        const float* As = sm + (t % STAGES) * STG_FLOATS;
        const float* Bs = As + A_STG;

        #pragma unroll
        for (int kk = 0; kk < BK; kk += 8) {
            uint32_t af[2][4], bf[8][2];
            #pragma unroll
            for (int mt = 0; mt < 2; mt++) {
                const float* p = As + (wm + mt * 16 + g) * AS_LD + kk + tg;
                af[mt][0] = __float_as_uint(p[0]);
                af[mt][1] = __float_as_uint(p[8 * AS_LD]);
                af[mt][2] = __float_as_uint(p[4]);
                af[mt][3] = __float_as_uint(p[8 * AS_LD + 4]);
            }
            #pragma unroll
            for (int j = 0; j < 8; j++) {
                const float* p = Bs + (kk + tg) * BS_LD + wn + j * 8 + g;
                bf[j][0] = __float_as_uint(p[0]);
                bf[j][1] = __float_as_uint(p[4 * BS_LD]);
            }
            #pragma unroll
            for (int mt = 0; mt < 2; mt++)
                #pragma unroll
                for (int j = 0; j < 8; j++)
                    mma_tf32(acc[mt][j], af[mt][0], af[mt][1], af[mt][2], af[mt][3],
                             bf[j][0], bf[j][1]);
        }
    }

    // Epilogue: += bias, (optionally tf32-round), store
    #pragma unroll
    for (int mt = 0; mt < 2; mt++) {
        int r0 = bm0 + wm + mt * 16 + g;
        #pragma unroll
        for (int j = 0; j < 8; j++) {
            int c0 = bn0 + wn + j * 8 + tg * 2;
            float2 bb = *(const float2*)(bias + c0);
            float o00 = acc[mt][j][0] + bb.x, o01 = acc[mt][j][1] + bb.y;
            float o10 = acc[mt][j][2] + bb.x, o11 = acc[mt][j][3] + bb.y;
            if (round_out) {
                o00 = tf32r(o00); o01 = tf32r(o01);
                o10 = tf32r(o10); o11 = tf32r(o11);
            }
            *(float2*)(C + (size_t)r0 * N + c0) = make_float2(o00, o01);
            *(float2*)(C + (size_t)(r0 + 8) * N + c0) = make_float2(o10, o11);
        }
    }
}

// ---------------------------------------------------------------------------
// Flash attention, 2-stage cp.async double buffer on K/V.
// Block = (64-query tile) x (b*h), 128 threads (4 warps).
// smem: sQ[64][68] (reused as P) + sK[2][64][68] + sV[2][64][72] = 89088 B
// ---------------------------------------------------------------------------
#define QP_LD 68
#define K_LD  68
#define V_LD  72
#define KBUF (64 * K_LD)
#define VBUF (64 * V_LD)
#define ATTN_SMEM ((64 * QP_LD + 2 * KBUF + 2 * VBUF) * 4)

__device__ __forceinline__ void attn_load_kv(
    float* sK, float* sV, const float* __restrict__ kbase,
    const float* __restrict__ vbase, int tid)
{
    #pragma unroll
    for (int i = 0; i < 8; i++) {
        int idx = tid + i * 128;
        int r = idx >> 4;
        int c = (idx & 15) << 2;
        cp16(sK + r * K_LD + c, kbase + (size_t)r * (3 * DM) + c);
    }
    #pragma unroll
    for (int i = 0; i < 8; i++) {
        int idx = tid + i * 128;
        int r = idx >> 4;
        int c = (idx & 15) << 2;
        cp16(sV + r * V_LD + c, vbase + (size_t)r * (3 * DM) + c);
    }
}

__global__ __launch_bounds__(128)
void attn_kernel()
{
    extern __shared__ __align__(16) float sm[];
    float* sQ  = sm;                      // also P after softmax
    float* sK0 = sm + 64 * QP_LD;
    float* sV0 = sK0 + 2 * KBUF;

    const int tid  = threadIdx.x;
    const int warp = tid >> 5;
    const int lane = tid & 31;
    const int g    = lane >> 2;
    const int tg   = lane & 3;
    const int qt   = blockIdx.x;
    const int bh   = blockIdx.y;
    const int b    = bh >> 4;
    const int h    = bh & 15;

    const float SCALE2 = 0.18033688011f;   // (1/8) * log2(e)

    const float* base = g_qkv + (size_t)b * SEQ * (3 * DM) + h * DH;

    // Q tile via cp.async (group 0)
    #pragma unroll
    for (int i = 0; i < 8; i++) {
        int idx = tid + i * 128;
        int r = idx >> 4;
        int c = (idx & 15) << 2;
        cp16(sQ + r * QP_LD + c, base + (size_t)(qt * 64 + r) * (3 * DM) + c);
    }
    cp_commit();

    // KV(0) (group 1)
    {
        const float* kbase = base + DM;
        attn_load_kv(sK0, sV0, kbase, kbase + DM, tid);
        cp_commit();
    }
    cp_wait<0>();
    __syncthreads();

    // Q fragments (warp-local rows of sQ)
    uint32_t qf[8][4];
    {
        const int m = warp * 16 + g;
        #pragma unroll
        for (int kk = 0; kk < 8; kk++) {
            const float* p = sQ + m * QP_LD + kk * 8 + tg;
            qf[kk][0] = __float_as_uint(p[0]);
            qf[kk][1] = __float_as_uint(p[8 * QP_LD]);
            qf[kk][2] = __float_as_uint(p[4]);
            qf[kk][3] = __float_as_uint(p[8 * QP_LD + 4]);
        }
    }

    float o[8][4];
    #pragma unroll
    for (int j = 0; j < 8; j++)
        #pragma unroll
        for (int e = 0; e < 4; e++) o[j][e] = 0.f;
    float m0 = NEG_INF, m1 = NEG_INF, l0 = 0.f, l1 = 0.f;

    for (int kt = 0; kt <= qt; kt++) {
        // prefetch next K/V into the other buffer
        if (kt + 1 <= qt) {
            const float* kb = base + DM + (size_t)(kt + 1) * 64 * (3 * DM);
            attn_load_kv(sK0 + ((kt + 1) & 1) * KBUF, sV0 + ((kt + 1) & 1) * VBUF,
                         kb, kb + DM, tid);
            cp_commit();
        }

        const float* sK = sK0 + (kt & 1) * KBUF;
        const float* sV = sV0 + (kt & 1) * VBUF;

        // S = Q @ K^T
        float c_[8][4];
        #pragma unroll
        for (int j = 0; j < 8; j++)
            #pragma unroll
            for (int e = 0; e < 4; e++) c_[j][e] = 0.f;

        #pragma unroll
        for (int kk = 0; kk < 8; kk++) {
            #pragma unroll
            for (int j = 0; j < 8; j++) {
                const float* p = sK + (j * 8 + g) * K_LD + kk * 8 + tg;
                mma_tf32(c_[j], qf[kk][0], qf[kk][1], qf[kk][2], qf[kk][3],
                         __float_as_uint(p[0]), __float_as_uint(p[4]));
            }
        }

        // scale into log2 domain + causal mask on diagonal tile
        if (kt == qt) {
            #pragma unroll
            for (int j = 0; j < 8; j++) {
                #pragma unroll
                for (int e = 0; e < 4; e++) {
                    int col = j * 8 + tg * 2 + (e & 1);
                    int row = warp * 16 + g + (e >> 1) * 8;
                    c_[j][e] = (col > row) ? NEG_INF : c_[j][e] * SCALE2;
                }
            }
        } else {
            #pragma unroll
            for (int j = 0; j < 8; j++)
                #pragma unroll
                for (int e = 0; e < 4; e++) c_[j][e] *= SCALE2;
        }

        // online softmax (base-2)
        float rx0 = NEG_INF, rx1 = NEG_INF;
        #pragma unroll
        for (int j = 0; j < 8; j++) {
            rx0 = fmaxf(rx0, fmaxf(c_[j][0], c_[j][1]));
            rx1 = fmaxf(rx1, fmaxf(c_[j][2], c_[j][3]));
        }
        rx0 = fmaxf(rx0, __shfl_xor_sync(0xffffffffu, rx0, 1));
        rx0 = fmaxf(rx0, __shfl_xor_sync(0xffffffffu, rx0, 2));
        rx1 = fmaxf(rx1, __shfl_xor_sync(0xffffffffu, rx1, 1));
        rx1 = fmaxf(rx1, __shfl_xor_sync(0xffffffffu, rx1, 2));

        float mn0 = fmaxf(m0, rx0), mn1 = fmaxf(m1, rx1);
        float al0 = ex2(m0 - mn0), al1 = ex2(m1 - mn1);
        float s0 = 0.f, s1 = 0.f;
        #pragma unroll
        for (int j = 0; j < 8; j++) {
            c_[j][0] = ex2(c_[j][0] - mn0);
            c_[j][1] = ex2(c_[j][1] - mn0);
            c_[j][2] = ex2(c_[j][2] - mn1);
            c_[j][3] = ex2(c_[j][3] - mn1);
            s0 += c_[j][0] + c_[j][1];
            s1 += c_[j][2] + c_[j][3];
        }
        s0 += __shfl_xor_sync(0xffffffffu, s0, 1);
        s0 += __shfl_xor_sync(0xffffffffu, s0, 2);
        s1 += __shfl_xor_sync(0xffffffffu, s1, 1);
        s1 += __shfl_xor_sync(0xffffffffu, s1, 2);
        l0 = l0 * al0 + s0;
        l1 = l1 * al1 + s1;
        m0 = mn0; m1 = mn1;
        #pragma unroll
        for (int j = 0; j < 8; j++) {
            o[j][0] *= al0; o[j][1] *= al0;
            o[j][2] *= al1; o[j][3] *= al1;
        }

        // stage P (tf32) into per-warp rows of sQ, then PV mma
        {
            const int rl = warp * 16 + g;
            #pragma unroll
            for (int j = 0; j < 8; j++) {
                float* p0 = sQ + rl * QP_LD + j * 8 + tg * 2;
                p0[0] = tf32r(c_[j][0]);
                p0[1] = tf32r(c_[j][1]);
                float* p1 = sQ + (rl + 8) * QP_LD + j * 8 + tg * 2;
                p1[0] = tf32r(c_[j][2]);
                p1[1] = tf32r(c_[j][3]);
            }
        }
        __syncwarp();

        #pragma unroll
        for (int kk = 0; kk < 8; kk++) {
            const float* pa = sQ + (warp * 16 + g) * QP_LD + kk * 8 + tg;
            uint32_t a0 = __float_as_uint(pa[0]);
            uint32_t a1 = __float_as_uint(pa[8 * QP_LD]);
            uint32_t a2 = __float_as_uint(pa[4]);
            uint32_t a3 = __float_as_uint(pa[8 * QP_LD + 4]);
            #pragma unroll
            for (int j = 0; j < 8; j++) {
                const float* pb = sV + (kk * 8 + tg) * V_LD + j * 8 + g;
                mma_tf32(o[j], a0, a1, a2, a3,
                         __float_as_uint(pb[0]), __float_as_uint(pb[4 * V_LD]));
            }
        }
        __syncwarp();

        if (kt + 1 <= qt) {
            cp_wait<0>();
            __syncthreads();
        }
    }

    // normalize, tf32-round, store
    const float inv0 = 1.f / l0, inv1 = 1.f / l1;
    const int srow = qt * 64 + warp * 16 + g;
    float* out0 = g_attn + ((size_t)b * SEQ + srow) * DM + h * DH;
    float* out1 = g_attn + ((size_t)b * SEQ + srow + 8) * DM + h * DH;
    #pragma unroll
    for (int j = 0; j < 8; j++) {
        int cl = j * 8 + tg * 2;
        *(float2*)(out0 + cl) = make_float2(tf32r(o[j][0] * inv0), tf32r(o[j][1] * inv0));
        *(float2*)(out1 + cl) = make_float2(tf32r(o[j][2] * inv1), tf32r(o[j][3] * inv1));
    }
}

// ---------------------------------------------------------------------------
// Launch
// ---------------------------------------------------------------------------
extern "C" void kernel_launch(void* const* d_in, const int* in_sizes, int n_in,
                              void* d_out, int out_size)
{
    (void)in_sizes; (void)n_in; (void)out_size;
    const float* x     = (const float*)d_in[0];
    const float* w_in  = (const float*)d_in[1];
    const float* b_in  = (const float*)d_in[2];
    const float* w_out = (const float*)d_in[3];
    const float* b_out = (const float*)d_in[4];
    float* out = (float*)d_out;

    float *qkv, *attn, *xr, *winr, *woutr;
    cudaGetSymbolAddress((void**)&qkv,   g_qkv);
    cudaGetSymbolAddress((void**)&attn,  g_attn);
    cudaGetSymbolAddress((void**)&xr,    g_x);
    cudaGetSymbolAddress((void**)&winr,  g_win);
    cudaGetSymbolAddress((void**)&woutr, g_wout);

    const int M = BATCH * SEQ;  // 8192

    // 0) pre-round inputs to tf32
    {
        int n4;
        n4 = (M * DM) / 4;
        round_tf32_kernel<<<(n4 + 255) / 256, 256>>>(x, xr, n4);
        n4 = (DM * 3 * DM) / 4;
        round_tf32_kernel<<<(n4 + 255) / 256, 256>>>(w_in, winr, n4);
        n4 = (DM * DM) / 4;
        round_tf32_kernel<<<(n4 + 255) / 256, 256>>>(w_out, woutr, n4);
    }

    static int attr_done = 0;
    if (!attr_done) {
        cudaFuncSetAttribute(gemm_bias_tf32, cudaFuncAttributeMaxDynamicSharedMemorySize, GEMM_SMEM);
        cudaFuncSetAttribute(attn_kernel, cudaFuncAttributeMaxDynamicSharedMemorySize, ATTN_SMEM);
        attr_done = 1;
    }

    // 1) QKV projection (tf32-rounded output)
    gemm_bias_tf32<<<dim3((3 * DM) / BN, M / BM), 256, GEMM_SMEM>>>(
        xr, winr, b_in, qkv, M, 3 * DM, DM, 1);

    // 2) causal flash attention (tf32-rounded output)
    attn_kernel<<<dim3(SEQ / 64, BATCH * NH), 128, ATTN_SMEM>>>();

    // 3) output projection (full f32 output)
    gemm_bias_tf32<<<dim3(DM / BN, M / BM), 256, GEMM_SMEM>>>(
        attn, woutr, b_out, out, M, DM, DM, 0);
}

// round 4
// speedup vs baseline: 1.1538x; 1.0178x over previous
#include <cuda_runtime.h>
#include <cstdint>

#define SEQ    2048
#define BATCH  4
#define DM     1024
#define NH     16
#define DH     64

// ---------------------------------------------------------------------------
// Scratch (allocation-free rule: __device__ globals)
// ---------------------------------------------------------------------------
__device__ float g_qkv[(size_t)BATCH * SEQ * 3 * DM];   // [B,S,3D] (tf32-rounded)
__device__ float g_attn[(size_t)BATCH * SEQ * DM];      // [B,S,D]  (tf32-rounded)
__device__ float g_x[(size_t)BATCH * SEQ * DM];         // tf32(x)
__device__ float g_winT[(size_t)3 * DM * DM];           // tf32(w_in)^T  [3D][D]
__device__ float g_woutT[(size_t)DM * DM];              // tf32(w_out)^T [D][D]

#define NEG_INF (__int_as_float(0xff800000))

__device__ __forceinline__ uint32_t f2tf(float x) {
    uint32_t u;
    asm volatile("cvt.rna.tf32.f32 %0, %1;" : "=r"(u) : "f"(x));
    return u;
}
__device__ __forceinline__ float tf32r(float x) { return __uint_as_float(f2tf(x)); }

__device__ __forceinline__ float ex2(float x) {
    float y;
    asm("ex2.approx.f32 %0, %1;" : "=f"(y) : "f"(x));
    return y;
}

__device__ __forceinline__ void mma_tf32(float c[4],
    uint32_t a0, uint32_t a1, uint32_t a2, uint32_t a3,
    uint32_t b0, uint32_t b1)
{
    asm volatile(
        "mma.sync.aligned.m16n8k8.row.col.f32.tf32.tf32.f32 "
        "{%0,%1,%2,%3}, {%4,%5,%6,%7}, {%8,%9}, {%0,%1,%2,%3};\n"
        : "+f"(c[0]), "+f"(c[1]), "+f"(c[2]), "+f"(c[3])
        : "r"(a0), "r"(a1), "r"(a2), "r"(a3), "r"(b0), "r"(b1));
}

// ldmatrix x4 (b16 form; moves 32-bit tf32 words with the standard
// (row = lane/4, word = lane%4) per-matrix distribution)
__device__ __forceinline__ void ldsm4(uint32_t* r, uint32_t addr) {
    asm volatile("ldmatrix.sync.aligned.m8n8.x4.shared.b16 {%0,%1,%2,%3}, [%4];"
        : "=r"(r[0]), "=r"(r[1]), "=r"(r[2]), "=r"(r[3]) : "r"(addr));
}

__device__ __forceinline__ void cp16(float* s, const float* g) {
    uint32_t sa = (uint32_t)__cvta_generic_to_shared(s);
    asm volatile("cp.async.cg.shared.global [%0], [%1], 16;\n" :: "r"(sa), "l"(g));
}
__device__ __forceinline__ void cp_commit() {
    asm volatile("cp.async.commit_group;\n");
}
template <int N>
__device__ __forceinline__ void cp_wait() {
    asm volatile("cp.async.wait_group %0;\n" :: "n"(N));
}
__device__ __forceinline__ uint32_t smem_u32(const void* p) {
    uint32_t a;
    asm("{ .reg .u64 t; cvta.to.shared.u64 t, %1; cvt.u32.u64 %0, t; }" : "=r"(a) : "l"(p));
    return a;
}

// ---------------------------------------------------------------------------
// Pre-passes: tf32 rounding, and tf32-rounding transpose (for weights)
// ---------------------------------------------------------------------------
__global__ void round_tf32_kernel(const float* __restrict__ in,
                                  float* __restrict__ out, int n4)
{
    int i = blockIdx.x * blockDim.x + threadIdx.x;
    if (i < n4) {
        float4 v = ((const float4*)in)[i];
        ((float4*)out)[i] = make_float4(tf32r(v.x), tf32r(v.y), tf32r(v.z), tf32r(v.w));
    }
}

// out[C][R] = tf32(in[R][C])^T ; block (32,8), grid (C/32, R/32)
__global__ void transpose_tf32_kernel(const float* __restrict__ in,
                                      float* __restrict__ out, int R, int C)
{
    __shared__ float t[32][33];
    int bx = blockIdx.x * 32;   // col block in `in`
    int by = blockIdx.y * 32;   // row block in `in`
    #pragma unroll
    for (int i = threadIdx.y; i < 32; i += 8)
        t[i][threadIdx.x] = in[(size_t)(by + i) * C + bx + threadIdx.x];
    __syncthreads();
    #pragma unroll
    for (int i = threadIdx.y; i < 32; i += 8)
        out[(size_t)(bx + i) * R + by + threadIdx.x] = tf32r(t[threadIdx.x][i]);
}

// ---------------------------------------------------------------------------
// GEMM: C[M,N] = A[M,K] @ Bt[N,K]^T + bias[N]   (tf32 mma.sync + ldmatrix)
// CTA tile 128x128, BK=32, 3-stage cp.async ring, 256 threads (8 warps,
// warp tile 32x64). Both A and B staged as [128][32] tiles, LD=36 pad
// (conflict-free for ldmatrix: 36 mod 32 = 4).
// ---------------------------------------------------------------------------
#define TLD 36
#define STG_FL (128 * TLD * 2)          // 9216 floats per stage (A then B)
#define GEMM_SMEM (3 * STG_FL * 4)      // 110592 bytes

__global__ __launch_bounds__(256, 2)
void gemm_tc(const float* __restrict__ A, const float* __restrict__ Bt,
             const float* __restrict__ bias, float* __restrict__ C,
             int M, int N, int K, int round_out)
{
    extern __shared__ __align__(16) float sm[];

    const int tid  = threadIdx.x;
    const int warp = tid >> 5;
    const int lane = tid & 31;
    const int g    = lane >> 2;
    const int tg   = lane & 3;
    const int wm   = (warp >> 1) * 32;
    const int wn   = (warp & 1) * 64;
    const int bm0  = blockIdx.y * 128;
    const int bn0  = blockIdx.x * 128;

    float acc[2][8][4];
    #pragma unroll
    for (int mt = 0; mt < 2; mt++)
        #pragma unroll
        for (int j = 0; j < 8; j++)
            #pragma unroll
            for (int e = 0; e < 4; e++) acc[mt][j][e] = 0.f;

    const int T = K >> 5;

    auto load_stage = [&](int slot, int kt) {
        float* As = sm + slot * STG_FL;
        float* Bs = As + 128 * TLD;
        #pragma unroll
        for (int i = 0; i < 4; i++) {
            int idx = tid + i * 256;
            int r = idx >> 3, c = (idx & 7) << 2;
            cp16(As + r * TLD + c, A + (size_t)(bm0 + r) * K + kt + c);
        }
        #pragma unroll
        for (int i = 0; i < 4; i++) {
            int idx = tid + i * 256;
            int r = idx >> 3, c = (idx & 7) << 2;
            cp16(Bs + r * TLD + c, Bt + (size_t)(bn0 + r) * K + kt + c);
        }
    };

    load_stage(0, 0);  cp_commit();
    load_stage(1, 32); cp_commit();

    const uint32_t sbase = smem_u32(sm);
    // ldmatrix per-lane address offsets (bytes)
    const uint32_t aOff = ((wm + (lane & 15)) * TLD + 4 * (lane >> 4)) * 4;
    const uint32_t bOff = (128 * TLD + (wn + (lane & 7)) * TLD + 4 * ((lane >> 3) & 3)) * 4;

    for (int t = 0; t < T; t++) {
        cp_wait<1>();
        __syncthreads();

        int tn = t + 2;
        if (tn < T) load_stage(tn % 3, tn * 32);
        cp_commit();

        const uint32_t stg = sbase + (uint32_t)((t % 3) * STG_FL * 4);

        #pragma unroll
        for (int kkH = 0; kkH < 2; kkH++) {     // two k16 halves of BK=32
            uint32_t af[2][2][4];
            #pragma unroll
            for (int mt = 0; mt < 2; mt++)
                #pragma unroll
                for (int sub = 0; sub < 2; sub++)
                    ldsm4(af[mt][sub],
                          stg + aOff + (uint32_t)((mt * 16 * TLD + kkH * 16 + sub * 8) * 4));
            #pragma unroll
            for (int j = 0; j < 8; j++) {
                uint32_t bf[4];
                ldsm4(bf, stg + bOff + (uint32_t)((j * 8 * TLD + kkH * 16) * 4));
                mma_tf32(acc[0][j], af[0][0][0], af[0][0][1], af[0][0][2], af[0][0][3], bf[0], bf[1]);
                mma_tf32(acc[1][j], af[1][0][0], af[1][0][1], af[1][0][2], af[1][0][3], bf[0], bf[1]);
                mma_tf32(acc[0][j], af[0][1][0], af[0][1][1], af[0][1][2], af[0][1][3], bf[2], bf[3]);
                mma_tf32(acc[1][j], af[1][1][0], af[1][1][1], af[1][1][2], af[1][1][3], bf[2], bf[3]);
            }
        }
    }

    // Epilogue: += bias, (optionally tf32-round), store
    #pragma unroll
    for (int mt = 0; mt < 2; mt++) {
        int r0 = bm0 + wm + mt * 16 + g;
        #pragma unroll
        for (int j = 0; j < 8; j++) {
            int c0 = bn0 + wn + j * 8 + tg * 2;
            float2 bb = *(const float2*)(bias + c0);
            float o00 = acc[mt][j][0] + bb.x, o01 = acc[mt][j][1] + bb.y;
            float o10 = acc[mt][j][2] + bb.x, o11 = acc[mt][j][3] + bb.y;
            if (round_out) {
                o00 = tf32r(o00); o01 = tf32r(o01);
                o10 = tf32r(o10); o11 = tf32r(o11);
            }
            *(float2*)(C + (size_t)r0 * N + c0) = make_float2(o00, o01);
            *(float2*)(C + (size_t)(r0 + 8) * N + c0) = make_float2(o10, o11);
        }
    }
}

// ---------------------------------------------------------------------------
// Flash attention: block = 128 queries x (b*h), 256 threads (8 warps).
// Warp w owns query rows 16w..16w+15. K fragments + P fragments via
// ldmatrix; V scalar. 2-stage cp.async double buffer on K/V.
// smem: sQP[128][68] + sK[2][64][68] + sV[2][64][72] = 106496 B
// ---------------------------------------------------------------------------
#define BQ 128
#define QP_LD 68
#define K_LD  68
#define V_LD  72
#define KBUF (64 * K_LD)
#define VBUF (64 * V_LD)
#define ATTN_SMEM ((BQ * QP_LD + 2 * KBUF + 2 * VBUF) * 4)

__device__ __forceinline__ void attn_load_kv(
    float* sK, float* sV, const float* __restrict__ kbase,
    const float* __restrict__ vbase, int tid)
{
    #pragma unroll
    for (int i = 0; i < 4; i++) {
        int idx = tid + i * 256;
        int r = idx >> 4, c = (idx & 15) << 2;
        cp16(sK + r * K_LD + c, kbase + (size_t)r * (3 * DM) + c);
    }
    #pragma unroll
    for (int i = 0; i < 4; i++) {
        int idx = tid + i * 256;
        int r = idx >> 4, c = (idx & 15) << 2;
        cp16(sV + r * V_LD + c, vbase + (size_t)r * (3 * DM) + c);
    }
}

__global__ __launch_bounds__(256, 1)
void attn_kernel()
{
    extern __shared__ __align__(16) float sm[];
    float* sQP = sm;                       // Q, then P staging
    float* sK0 = sm + BQ * QP_LD;
    float* sV0 = sK0 + 2 * KBUF;

    const int tid  = threadIdx.x;
    const int warp = tid >> 5;
    const int lane = tid & 31;
    const int g    = lane >> 2;
    const int tg   = lane & 3;
    const int qt   = blockIdx.x;           // 0..15 (128-query tiles)
    const int bh   = blockIdx.y;
    const int b    = bh >> 4;
    const int h    = bh & 15;
    const int q0   = qt * BQ;

    const float SCALE2 = 0.18033688011f;   // (1/8) * log2(e)

    const float* base = g_qkv + (size_t)b * SEQ * (3 * DM) + h * DH;

    // Q tile (128 x 64) via cp.async
    #pragma unroll
    for (int i = 0; i < 8; i++) {
        int idx = tid + i * 256;
        int r = idx >> 4, c = (idx & 15) << 2;
        cp16(sQP + r * QP_LD + c, base + (size_t)(q0 + r) * (3 * DM) + c);
    }
    cp_commit();
    {
        const float* kbase = base + DM;
        attn_load_kv(sK0, sV0, kbase, kbase + DM, tid);
        cp_commit();
    }
    cp_wait<0>();
    __syncthreads();

    const uint32_t sbase = smem_u32(sm);
    // A-operand ldmatrix lane offset within this warp's 16 rows of sQP
    const uint32_t pBase = sbase +
        (uint32_t)(((warp * 16 + (lane & 15)) * QP_LD + 4 * (lane >> 4)) * 4);
    // B-operand (K tile) ldmatrix lane offset (row/col within 64x64 tile)
    const uint32_t kLane = (uint32_t)((((lane & 7)) * K_LD + 4 * ((lane >> 3) & 3)) * 4);

    // Q fragments: 8 k8-steps over dh=64
    uint32_t qf[8][4];
    #pragma unroll
    for (int kk = 0; kk < 8; kk++)
        ldsm4(qf[kk], pBase + (uint32_t)(kk * 8 * 4));

    float o[8][4];
    #pragma unroll
    for (int j = 0; j < 8; j++)
        #pragma unroll
        for (int e = 0; e < 4; e++) o[j][e] = 0.f;
    float m0 = NEG_INF, m1 = NEG_INF, l0 = 0.f, l1 = 0.f;

    const int tiles = 2 * qt + 2;
    for (int kt = 0; kt < tiles; kt++) {
        if (kt + 1 < tiles) {
            const float* kb = base + DM + (size_t)(kt + 1) * 64 * (3 * DM);
            attn_load_kv(sK0 + ((kt + 1) & 1) * KBUF, sV0 + ((kt + 1) & 1) * VBUF,
                         kb, kb + DM, tid);
            cp_commit();
        }

        const uint32_t kB = sbase + (uint32_t)((BQ * QP_LD + (kt & 1) * KBUF) * 4) + kLane;
        const float* sV = sV0 + (kt & 1) * VBUF;

        // S = Q @ K^T  via ldmatrix B fragments
        float c_[8][4];
        #pragma unroll
        for (int j = 0; j < 8; j++)
            #pragma unroll
            for (int e = 0; e < 4; e++) c_[j][e] = 0.f;

        #pragma unroll
        for (int kkH = 0; kkH < 4; kkH++) {
            #pragma unroll
            for (int j = 0; j < 8; j++) {
                uint32_t bf[4];
                ldsm4(bf, kB + (uint32_t)((j * 8 * K_LD + kkH * 16) * 4));
                mma_tf32(c_[j], qf[2*kkH][0], qf[2*kkH][1], qf[2*kkH][2], qf[2*kkH][3],
                         bf[0], bf[1]);
                mma_tf32(c_[j], qf[2*kkH+1][0], qf[2*kkH+1][1], qf[2*kkH+1][2], qf[2*kkH+1][3],
                         bf[2], bf[3]);
            }
        }

        // scale (log2 domain) + causal mask (only last two tiles can clip)
        if (kt >= 2 * qt) {
            #pragma unroll
            for (int j = 0; j < 8; j++) {
                #pragma unroll
                for (int e = 0; e < 4; e++) {
                    int col = kt * 64 + j * 8 + tg * 2 + (e & 1);
                    int row = q0 + warp * 16 + g + (e >> 1) * 8;
                    c_[j][e] = (col > row) ? NEG_INF : c_[j][e] * SCALE2;
                }
            }
        } else {
            #pragma unroll
            for (int j = 0; j < 8; j++)
                #pragma unroll
                for (int e = 0; e < 4; e++) c_[j][e] *= SCALE2;
        }

        // online softmax (base-2), rows g and g+8
        float rx0 = NEG_INF, rx1 = NEG_INF;
        #pragma unroll
        for (int j = 0; j < 8; j++) {
            rx0 = fmaxf(rx0, fmaxf(c_[j][0], c_[j][1]));
            rx1 = fmaxf(rx1, fmaxf(c_[j][2], c_[j][3]));
        }
        rx0 = fmaxf(rx0, __shfl_xor_sync(0xffffffffu, rx0, 1));
        rx0 = fmaxf(rx0, __shfl_xor_sync(0xffffffffu, rx0, 2));
        rx1 = fmaxf(rx1, __shfl_xor_sync(0xffffffffu, rx1, 1));
        rx1 = fmaxf(rx1, __shfl_xor_sync(0xffffffffu, rx1, 2));

        float mn0 = fmaxf(m0, rx0), mn1 = fmaxf(m1, rx1);
        float al0 = ex2(m0 - mn0), al1 = ex2(m1 - mn1);
        float s0 = 0.f, s1 = 0.f;
        #pragma unroll
        for (int j = 0; j < 8; j++) {
            c_[j][0] = ex2(c_[j][0] - mn0);
            c_[j][1] = ex2(c_[j][1] - mn0);
            c_[j][2] = ex2(c_[j][2] - mn1);
            c_[j][3] = ex2(c_[j][3] - mn1);
            s0 += c_[j][0] + c_[j][1];
            s1 += c_[j][2] + c_[j][3];
        }
        s0 += __shfl_xor_sync(0xffffffffu, s0, 1);
        s0 += __shfl_xor_sync(0xffffffffu, s0, 2);
        s1 += __shfl_xor_sync(0xffffffffu, s1, 1);
        s1 += __shfl_xor_sync(0xffffffffu, s1, 2);
        l0 = l0 * al0 + s0;
        l1 = l1 * al1 + s1;
        m0 = mn0; m1 = mn1;
        #pragma unroll
        for (int j = 0; j < 8; j++) {
            o[j][0] *= al0; o[j][1] *= al0;
            o[j][2] *= al1; o[j][3] *= al1;
        }

        // stage P (tf32) into this warp's rows of sQP (float2 stores)
        {
            const int rl = warp * 16 + g;
            #pragma unroll
            for (int j = 0; j < 8; j++) {
                *(float2*)(sQP + rl * QP_LD + j * 8 + tg * 2) =
                    make_float2(tf32r(c_[j][0]), tf32r(c_[j][1]));
                *(float2*)(sQP + (rl + 8) * QP_LD + j * 8 + tg * 2) =
                    make_float2(tf32r(c_[j][2]), tf32r(c_[j][3]));
            }
        }
        __syncwarp();

        // O += P @ V   (P fragments via ldmatrix, V scalar)
        #pragma unroll
        for (int kk = 0; kk < 8; kk++) {
            uint32_t pf[4];
            ldsm4(pf, pBase + (uint32_t)(kk * 8 * 4));
            #pragma unroll
            for (int j = 0; j < 8; j++) {
                const float* pb = sV + (kk * 8 + tg) * V_LD + j * 8 + g;
                mma_tf32(o[j], pf[0], pf[1], pf[2], pf[3],
                         __float_as_uint(pb[0]), __float_as_uint(pb[4 * V_LD]));
            }
        }
        __syncwarp();

        if (kt + 1 < tiles) {
            cp_wait<0>();
            __syncthreads();
        }
    }

    // normalize, tf32-round, store
    const float inv0 = 1.f / l0, inv1 = 1.f / l1;
    const int srow = q0 + warp * 16 + g;
    float* out0 = g_attn + ((size_t)b * SEQ + srow) * DM + h * DH;
    float* out1 = g_attn + ((size_t)b * SEQ + srow + 8) * DM + h * DH;
    #pragma unroll
    for (int j = 0; j < 8; j++) {
        int cl = j * 8 + tg * 2;
        *(float2*)(out0 + cl) = make_float2(tf32r(o[j][0] * inv0), tf32r(o[j][1] * inv0));
        *(float2*)(out1 + cl) = make_float2(tf32r(o[j][2] * inv1), tf32r(o[j][3] * inv1));
    }
}

// ---------------------------------------------------------------------------
// Launch
// ---------------------------------------------------------------------------
extern "C" void kernel_launch(void* const* d_in, const int* in_sizes, int n_in,
                              void* d_out, int out_size)
{
    (void)in_sizes; (void)n_in; (void)out_size;
    const float* x     = (const float*)d_in[0];
    const float* w_in  = (const float*)d_in[1];
    const float* b_in  = (const float*)d_in[2];
    const float* w_out = (const float*)d_in[3];
    const float* b_out = (const float*)d_in[4];
    float* out = (float*)d_out;

    float *qkv, *attn, *xr, *winT, *woutT;
    cudaGetSymbolAddress((void**)&qkv,   g_qkv);
    cudaGetSymbolAddress((void**)&attn,  g_attn);
    cudaGetSymbolAddress((void**)&xr,    g_x);
    cudaGetSymbolAddress((void**)&winT,  g_winT);
    cudaGetSymbolAddress((void**)&woutT, g_woutT);

    const int M = BATCH * SEQ;  // 8192

    cudaFuncSetAttribute(gemm_tc, cudaFuncAttributeMaxDynamicSharedMemorySize, GEMM_SMEM);
    cudaFuncSetAttribute(attn_kernel, cudaFuncAttributeMaxDynamicSharedMemorySize, ATTN_SMEM);

    // 0) pre-round x; pre-transpose (+round) weights
    {
        int n4 = (M * DM) / 4;
        round_tf32_kernel<<<(n4 + 255) / 256, 256>>>(x, xr, n4);
        transpose_tf32_kernel<<<dim3((3 * DM) / 32, DM / 32), dim3(32, 8)>>>(
            w_in, winT, DM, 3 * DM);
        transpose_tf32_kernel<<<dim3(DM / 32, DM / 32), dim3(32, 8)>>>(
            w_out, woutT, DM, DM);
    }

    // 1) QKV projection (tf32-rounded output)
    gemm_tc<<<dim3((3 * DM) / 128, M / 128), 256, GEMM_SMEM>>>(
        xr, winT, b_in, qkv, M, 3 * DM, DM, 1);

    // 2) causal flash attention (tf32-rounded output)
    attn_kernel<<<dim3(SEQ / BQ, BATCH * NH), 256, ATTN_SMEM>>>();

    // 3) output projection (full f32 output)
    gemm_tc<<<dim3(DM / 128, M / 128), 256, GEMM_SMEM>>>(
        attn, woutT, b_out, out, M, DM, DM, 0);
}